// round 15
// baseline (speedup 1.0000x reference)
#include <cuda_runtime.h>
#include <cuda_fp16.h>

// GAT over 16384 independent 32-node cliques, fully fused: one CTA per graph.
// fp16 tensor cores; scores folded into GEMMs; ldmatrix fragment loads.
// This round: register diet (weights loaded as per-kt uint2 inside the nt
// loop) + __launch_bounds__(128,8) to lift occupancy from 6 to 8 CTAs/SM.

#define NCOL 32
#define HEADS 4
#define FH 128
#define HSTR 136        // hs row stride in halfs
#define F3 24
#define XSTR 24
#define ASTRW 20        // alpha row stride in u32 words
#define THREADS 128
#define NEG_SLOPE 0.2f

typedef unsigned long long u64;

__device__ unsigned W2h_g[8192];   // [(unit*8+kt)*32+lane]*2+sel  (uint2 per (lane,kt))
__device__ unsigned W1h_g[1024];
__device__ unsigned W3h_g[2048];   // [(w*8+kt)*32+lane]*2+sel
__device__ unsigned U1f_g[64];
__device__ unsigned U2f_g[512];    // [(m*32+lane)*4+j]
__device__ unsigned U3f_g[512];

__device__ __forceinline__ float lrelu(float x) { return fmaxf(x, NEG_SLOPE * x); }

__device__ __forceinline__ u64 pack2(float a, float b) {
    u64 r; asm("mov.b64 %0,{%1,%2};" : "=l"(r) : "f"(a), "f"(b)); return r;
}
__device__ __forceinline__ float2 unpack2(u64 v) {
    float2 r; asm("mov.b64 {%0,%1},%2;" : "=f"(r.x), "=f"(r.y) : "l"(v)); return r;
}
__device__ __forceinline__ void add2(u64 &d, u64 a) {
    asm("add.rn.f32x2 %0,%0,%1;" : "+l"(d) : "l"(a));
}
__device__ __forceinline__ u64 shfl_xor_u64(u64 v, int m) {
    unsigned lo, hi;
    asm("mov.b64 {%0,%1},%2;" : "=r"(lo), "=r"(hi) : "l"(v));
    lo = __shfl_xor_sync(0xffffffffu, lo, m);
    hi = __shfl_xor_sync(0xffffffffu, hi, m);
    u64 r; asm("mov.b64 %0,{%1,%2};" : "=l"(r) : "r"(lo), "r"(hi));
    return r;
}
__device__ __forceinline__ unsigned packh2(float lo, float hi) {
    __half2 h = __floats2half2_rn(lo, hi);
    return *(unsigned*)&h;
}
__device__ __forceinline__ void mma_h(float c[4], const unsigned a[4], const unsigned b[2]) {
    asm("mma.sync.aligned.m16n8k16.row.col.f32.f16.f16.f32 "
        "{%0,%1,%2,%3}, {%4,%5,%6,%7}, {%8,%9}, {%0,%1,%2,%3};"
        : "+f"(c[0]), "+f"(c[1]), "+f"(c[2]), "+f"(c[3])
        : "r"(a[0]), "r"(a[1]), "r"(a[2]), "r"(a[3]), "r"(b[0]), "r"(b[1]));
}
__device__ __forceinline__ unsigned sptr(const void* p) {
    unsigned a;
    asm("{ .reg .u64 t; cvta.to.shared.u64 t, %1; cvt.u32.u64 %0, t; }" : "=r"(a) : "l"(p));
    return a;
}
__device__ __forceinline__ void ldsm_x4_trans(unsigned &d0, unsigned &d1,
                                              unsigned &d2, unsigned &d3, unsigned addr) {
    asm volatile("ldmatrix.sync.aligned.m8n8.x4.trans.shared.b16 {%0,%1,%2,%3}, [%4];"
                 : "=r"(d0), "=r"(d1), "=r"(d2), "=r"(d3) : "r"(addr));
}
__device__ __forceinline__ void ldsm_x4(unsigned a[4], unsigned addr) {
    asm volatile("ldmatrix.sync.aligned.m8n8.x4.shared.b16 {%0,%1,%2,%3}, [%4];"
                 : "=r"(a[0]), "=r"(a[1]), "=r"(a[2]), "=r"(a[3]) : "r"(addr));
}

__device__ __forceinline__ void store_scores(const float Cs[2][4],
                                             float* __restrict__ s_src,
                                             float* __restrict__ s_dst,
                                             int w, int qr, int qc)
{
    const int par = w & 1;
    if (qc == (w >> 1)) {
        s_src[32 * w + qr]      = par ? Cs[0][1] : Cs[0][0];
        s_src[32 * w + qr + 8]  = par ? Cs[0][3] : Cs[0][2];
        s_src[32 * w + qr + 16] = par ? Cs[1][1] : Cs[1][0];
        s_src[32 * w + qr + 24] = par ? Cs[1][3] : Cs[1][2];
    }
    if (qc == 2 + (w >> 1)) {
        s_dst[32 * w + qr]      = par ? Cs[0][1] : Cs[0][0];
        s_dst[32 * w + qr + 8]  = par ? Cs[0][3] : Cs[0][2];
        s_dst[32 * w + qr + 16] = par ? Cs[1][1] : Cs[1][0];
        s_dst[32 * w + qr + 24] = par ? Cs[1][3] : Cs[1][2];
    }
}

__global__ void prep_kernel(const float* __restrict__ W1, const float* __restrict__ W2,
                            const float* __restrict__ W3,
                            const float* __restrict__ as1, const float* __restrict__ ad1,
                            const float* __restrict__ as2, const float* __restrict__ ad2,
                            const float* __restrict__ as3, const float* __restrict__ ad3)
{
    int idx = blockIdx.x * blockDim.x + threadIdx.x;
    if (idx < 8192) {            // W2h: word = ((unit*8+kt)*32+lane)*2+sel
        int sel = idx & 1;
        int i2 = idx >> 1;
        int lane = i2 & 31, kt = (i2 >> 5) & 7, unit = i2 >> 8;
        int qr = lane >> 2, qc = lane & 3;
        int w = unit >> 2, nt = unit & 3;
        int kp = 16 * kt + 2 * qc + (sel ? 8 : 0);
        int col = 32 * w + 8 * nt + qr;
        W2h_g[idx] = packh2(W2[kp * FH + col], W2[(kp + 1) * FH + col]);
    } else if (idx < 9216) {     // W1h
        int i = idx - 8192;
        int j = i & 1, lane = (i >> 1) & 31, unit = i >> 6;
        int qr = lane >> 2, qc = lane & 3;
        int w = unit >> 2, nt = unit & 3;
        int kp = 2 * qc + (j ? 8 : 0);
        int col = 32 * w + 8 * nt + qr;
        W1h_g[i] = packh2(W1[kp * FH + col], W1[(kp + 1) * FH + col]);
    } else if (idx < 11264) {    // W3h: word = ((w*8+kt)*32+lane)*2+sel
        int i = idx - 9216;
        int sel = i & 1;
        int i2 = i >> 1;
        int lane = i2 & 31, kt = (i2 >> 5) & 7, w = i2 >> 8;
        int qr = lane >> 2, qc = lane & 3;
        int kp = 16 * kt + 2 * qc + (sel ? 8 : 0);
        W3h_g[i] = (qr < 6) ? packh2(W3[kp * F3 + w * 6 + qr], W3[(kp + 1) * F3 + w * 6 + qr]) : 0u;
    } else if (idx < 11776) {    // U2f
        int i = idx - 11264;
        int jj = i & 3, lane = (i >> 2) & 31, m = i >> 7;
        int qr = lane >> 2, qc = lane & 3;
        int kt = 2 * m + (jj >> 1);
        int kp = 16 * kt + 2 * qc + ((jj & 1) ? 8 : 0);
        const float* av = (qr < 4) ? (as2 + 32 * qr) : (ad2 + 32 * (qr - 4));
        int h = qr & 3;
        float u0 = 0.f, u1 = 0.f;
        for (int d = 0; d < 32; d++) {
            u0 += W2[kp * FH + 32 * h + d] * av[d];
            u1 += W2[(kp + 1) * FH + 32 * h + d] * av[d];
        }
        U2f_g[i] = packh2(u0, u1);
    } else if (idx < 11840) {    // U1f
        int i = idx - 11776;
        int jj = i & 1, lane = i >> 1;
        int qr = lane >> 2, qc = lane & 3;
        int kp = 2 * qc + (jj ? 8 : 0);
        const float* av = (qr < 4) ? (as1 + 32 * qr) : (ad1 + 32 * (qr - 4));
        int h = qr & 3;
        float u0 = 0.f, u1 = 0.f;
        for (int d = 0; d < 32; d++) {
            u0 += W1[kp * FH + 32 * h + d] * av[d];
            u1 += W1[(kp + 1) * FH + 32 * h + d] * av[d];
        }
        U1f_g[i] = packh2(u0, u1);
    } else if (idx < 12352) {    // U3f
        int i = idx - 11840;
        int jj = i & 3, lane = (i >> 2) & 31, m = i >> 7;
        int qr = lane >> 2, qc = lane & 3;
        int kt = 2 * m + (jj >> 1);
        int kp = 16 * kt + 2 * qc + ((jj & 1) ? 8 : 0);
        const float* av = (qr < 4) ? (as3 + 6 * qr) : (ad3 + 6 * (qr - 4));
        int h = qr & 3;
        float u0 = 0.f, u1 = 0.f;
        for (int d = 0; d < 6; d++) {
            u0 += W3[kp * F3 + 6 * h + d] * av[d];
            u1 += W3[(kp + 1) * F3 + 6 * h + d] * av[d];
        }
        U3f_g[i] = packh2(u0, u1);
    }
}

__global__ void __launch_bounds__(THREADS, 8) gat_fused_kernel(
    const float* __restrict__ xs,
    const float* __restrict__ pe,
    const float* __restrict__ b1,
    const float* __restrict__ b2,
    const float* __restrict__ b3,
    const float* __restrict__ lw,
    const float* __restrict__ lb,
    float* __restrict__ out,
    int R)
{
    __shared__ __half hs[NCOL][HSTR];
    __shared__ unsigned alphas[HEADS][NCOL][ASTRW];
    __shared__ float s_src[HEADS * NCOL];
    __shared__ float s_dst[HEADS * NCOL];
    __shared__ float cs[F3];

    __half (*xin)[XSTR] = (__half(*)[XSTR]) & alphas[0][0][0];  // overlay

    const int g = blockIdx.x;
    const int b = g / R;
    const int r = g - b * R;
    const int t = threadIdx.x;
    const int lane = t & 31;
    const int w = t >> 5;
    const int qr = lane >> 2;
    const int qc = lane & 3;
    const int lrow = lane & 15;
    const int lkoff = (lane >> 4) << 3;

    // ---- build input features (fp16) ----
    for (int idx = t; idx < NCOL * 16; idx += THREADS) {
        int n = idx >> 4, f = idx & 15;
        float v;
        if (f == 0) v = xs[(size_t)(b * R + r) * NCOL + n];
        else        v = pe[(b * NCOL + n) * 15 + (f - 1)];
        xin[n][f] = __float2half_rn(v);
    }
    __syncthreads();

    // ================= layer 1 GEMM + scores =================
    {
        float C[2][4][4];
        float Cs[2][4];
#pragma unroll
        for (int mb = 0; mb < 2; mb++) {
#pragma unroll
            for (int nt = 0; nt < 4; nt++)
#pragma unroll
                for (int i = 0; i < 4; i++) C[mb][nt][i] = 0.f;
#pragma unroll
            for (int i = 0; i < 4; i++) Cs[mb][i] = 0.f;
        }

        unsigned a[2][4];
#pragma unroll
        for (int mb = 0; mb < 2; mb++)
            ldsm_x4(a[mb], sptr(&xin[16 * mb + lrow][lkoff]));

        const uint2* W1h2 = (const uint2*)W1h_g;
#pragma unroll
        for (int nt = 0; nt < 4; nt++) {
            uint2 bw = W1h2[(w * 4 + nt) * 32 + lane];
            unsigned bf[2] = { bw.x, bw.y };
#pragma unroll
            for (int mb = 0; mb < 2; mb++) mma_h(C[mb][nt], a[mb], bf);
        }
        {
            uint2 uw = ((const uint2*)U1f_g)[lane];
            unsigned bf[2] = { uw.x, uw.y };
#pragma unroll
            for (int mb = 0; mb < 2; mb++) mma_h(Cs[mb], a[mb], bf);
        }
#pragma unroll
        for (int mb = 0; mb < 2; mb++)
#pragma unroll
            for (int nt = 0; nt < 4; nt++) {
                const int c = 32 * w + 8 * nt + 2 * qc;
                *(unsigned*)&hs[16 * mb + qr][c]     = packh2(C[mb][nt][0], C[mb][nt][1]);
                *(unsigned*)&hs[16 * mb + qr + 8][c] = packh2(C[mb][nt][2], C[mb][nt][3]);
            }
        store_scores(Cs, s_src, s_dst, w, qr, qc);
    }
    __syncthreads();

    // ================= attention layers 1 & 2 + following GEMM =================
#pragma unroll
    for (int layer = 0; layer < 2; layer++) {
        const float* bias = layer ? b2 : b1;
        const int c0 = 32 * w;
        __syncwarp();

        // softmax (no max-pass)
        {
            const float sdst = s_dst[w * NCOL + lane];
            float e[NCOL];
            float sum = 0.f;
#pragma unroll
            for (int q = 0; q < 8; q++) {
                float4 sv = *(const float4*)&s_src[w * NCOL + 4 * q];
                e[4*q+0] = __expf(lrelu(sdst + sv.x));
                e[4*q+1] = __expf(lrelu(sdst + sv.y));
                e[4*q+2] = __expf(lrelu(sdst + sv.z));
                e[4*q+3] = __expf(lrelu(sdst + sv.w));
                sum += e[4*q+0] + e[4*q+1] + e[4*q+2] + e[4*q+3];
            }
            const float rinv = 1.f / sum;
#pragma unroll
            for (int q = 0; q < 4; q++) {
                uint4 v;
                v.x = packh2(e[8*q+0] * rinv, e[8*q+1] * rinv);
                v.y = packh2(e[8*q+2] * rinv, e[8*q+3] * rinv);
                v.z = packh2(e[8*q+4] * rinv, e[8*q+5] * rinv);
                v.w = packh2(e[8*q+6] * rinv, e[8*q+7] * rinv);
                *(uint4*)&alphas[w][lane][4 * q] = v;
            }
        }
        __syncwarp();

        // aggregation MMA: out(32x32) = alpha @ h_head, in-place (warp-local cols)
        {
            float C[2][4][4];
#pragma unroll
            for (int mb = 0; mb < 2; mb++)
#pragma unroll
                for (int nt = 0; nt < 4; nt++)
#pragma unroll
                    for (int i = 0; i < 4; i++) C[mb][nt][i] = 0.f;

            unsigned af[2][2][4];
#pragma unroll
            for (int kt = 0; kt < 2; kt++)
#pragma unroll
                for (int mb = 0; mb < 2; mb++)
                    ldsm_x4(af[kt][mb],
                            sptr((const __half*)&alphas[w][16 * mb + lrow][0] + 16 * kt + lkoff));
#pragma unroll
            for (int nt = 0; nt < 4; nt++) {
                unsigned d0, d1, d2, d3;
                ldsm_x4_trans(d0, d1, d2, d3, sptr(&hs[lane][c0 + 8 * nt]));
                unsigned bf0[2] = { d0, d1 };
                unsigned bf1[2] = { d2, d3 };
#pragma unroll
                for (int mb = 0; mb < 2; mb++) {
                    mma_h(C[mb][nt], af[0][mb], bf0);
                    mma_h(C[mb][nt], af[1][mb], bf1);
                }
            }
#pragma unroll
            for (int nt = 0; nt < 4; nt++) {
                const int c = c0 + 8 * nt + 2 * qc;
                float bb0 = bias[c], bb1 = bias[c + 1];
#pragma unroll
                for (int mb = 0; mb < 2; mb++) {
                    *(unsigned*)&hs[16 * mb + qr][c] =
                        packh2(C[mb][nt][0] + bb0, C[mb][nt][1] + bb1);
                    *(unsigned*)&hs[16 * mb + qr + 8][c] =
                        packh2(C[mb][nt][2] + bb0, C[mb][nt][3] + bb1);
                }
            }
        }
        __syncthreads();

        if (layer == 0) {
            // ---- layer 2 GEMM + scores (register-lean weight loads) ----
            float C[2][4][4];
            float Cs[2][4];
#pragma unroll
            for (int mb = 0; mb < 2; mb++) {
#pragma unroll
                for (int nt = 0; nt < 4; nt++)
#pragma unroll
                    for (int i = 0; i < 4; i++) C[mb][nt][i] = 0.f;
#pragma unroll
                for (int i = 0; i < 4; i++) Cs[mb][i] = 0.f;
            }

            const uint2* W2h2 = (const uint2*)W2h_g;
            const uint4* U2f4 = (const uint4*)U2f_g;
#pragma unroll
            for (int m = 0; m < 4; m++) {
                uint4 uv = U2f4[m * 32 + lane];
#pragma unroll
                for (int hh = 0; hh < 2; hh++) {
                    const int kt = 2 * m + hh;
                    unsigned a[2][4];
#pragma unroll
                    for (int mb = 0; mb < 2; mb++)
                        ldsm_x4(a[mb], sptr(&hs[16 * mb + lrow][16 * kt + lkoff]));
#pragma unroll
                    for (int nt = 0; nt < 4; nt++) {
                        uint2 bw = W2h2[((w * 4 + nt) * 8 + kt) * 32 + lane];  // coalesced
                        unsigned bf[2] = { bw.x, bw.y };
#pragma unroll
                        for (int mb = 0; mb < 2; mb++) mma_h(C[mb][nt], a[mb], bf);
                    }
                    {
                        unsigned bf[2];
                        if (hh == 0) { bf[0] = uv.x; bf[1] = uv.y; }
                        else         { bf[0] = uv.z; bf[1] = uv.w; }
#pragma unroll
                        for (int mb = 0; mb < 2; mb++) mma_h(Cs[mb], a[mb], bf);
                    }
                }
            }
            __syncthreads();
#pragma unroll
            for (int mb = 0; mb < 2; mb++)
#pragma unroll
                for (int nt = 0; nt < 4; nt++) {
                    const int c = 32 * w + 8 * nt + 2 * qc;
                    *(unsigned*)&hs[16 * mb + qr][c]     = packh2(C[mb][nt][0], C[mb][nt][1]);
                    *(unsigned*)&hs[16 * mb + qr + 8][c] = packh2(C[mb][nt][2], C[mb][nt][3]);
                }
            store_scores(Cs, s_src, s_dst, w, qr, qc);
        } else {
            // ---- layer 3 GEMM (padded cols 8w..8w+7) + scores ----
            float C[2][4];
            float Cs[2][4];
#pragma unroll
            for (int mb = 0; mb < 2; mb++)
#pragma unroll
                for (int i = 0; i < 4; i++) { C[mb][i] = 0.f; Cs[mb][i] = 0.f; }

            const uint2* W3h2 = (const uint2*)W3h_g;
            const uint4* U3f4 = (const uint4*)U3f_g;
#pragma unroll
            for (int m = 0; m < 4; m++) {
                uint4 uv = U3f4[m * 32 + lane];
#pragma unroll
                for (int hh = 0; hh < 2; hh++) {
                    const int kt = 2 * m + hh;
                    unsigned a[2][4];
#pragma unroll
                    for (int mb = 0; mb < 2; mb++)
                        ldsm_x4(a[mb], sptr(&hs[16 * mb + lrow][16 * kt + lkoff]));
                    uint2 bw = W3h2[(w * 8 + kt) * 32 + lane];  // coalesced
                    unsigned bf[2] = { bw.x, bw.y };
                    unsigned bu[2];
                    if (hh == 0) { bu[0] = uv.x; bu[1] = uv.y; }
                    else         { bu[0] = uv.z; bu[1] = uv.w; }
#pragma unroll
                    for (int mb = 0; mb < 2; mb++) {
                        mma_h(C[mb], a[mb], bf);
                        mma_h(Cs[mb], a[mb], bu);
                    }
                }
            }
            __syncthreads();
#pragma unroll
            for (int mb = 0; mb < 2; mb++) {
                const int c = 8 * w + 2 * qc;
                *(unsigned*)&hs[16 * mb + qr][c]     = packh2(C[mb][0], C[mb][1]);
                *(unsigned*)&hs[16 * mb + qr + 8][c] = packh2(C[mb][2], C[mb][3]);
            }
            store_scores(Cs, s_src, s_dst, w, qr, qc);
        }
    }
    __syncwarp();

    // ================= layer-3 attention + register tail =================
    {
        const int cp = 8 * w;

        // softmax (no max-pass)
        {
            const float sdst = s_dst[w * NCOL + lane];
            float e[NCOL];
            float sum = 0.f;
#pragma unroll
            for (int q = 0; q < 8; q++) {
                float4 sv = *(const float4*)&s_src[w * NCOL + 4 * q];
                e[4*q+0] = __expf(lrelu(sdst + sv.x));
                e[4*q+1] = __expf(lrelu(sdst + sv.y));
                e[4*q+2] = __expf(lrelu(sdst + sv.z));
                e[4*q+3] = __expf(lrelu(sdst + sv.w));
                sum += e[4*q+0] + e[4*q+1] + e[4*q+2] + e[4*q+3];
            }
            const float rinv = 1.f / sum;
#pragma unroll
            for (int q = 0; q < 4; q++) {
                uint4 v;
                v.x = packh2(e[8*q+0] * rinv, e[8*q+1] * rinv);
                v.y = packh2(e[8*q+2] * rinv, e[8*q+3] * rinv);
                v.z = packh2(e[8*q+4] * rinv, e[8*q+5] * rinv);
                v.w = packh2(e[8*q+6] * rinv, e[8*q+7] * rinv);
                *(uint4*)&alphas[w][lane][4 * q] = v;
            }
        }
        __syncwarp();

        // MMA: h3post = alpha @ h3 (N=8 padded); C stays in registers
        float C[2][4];
#pragma unroll
        for (int mb = 0; mb < 2; mb++)
#pragma unroll
            for (int i = 0; i < 4; i++) C[mb][i] = 0.f;

        unsigned af[2][2][4];
#pragma unroll
        for (int kt = 0; kt < 2; kt++)
#pragma unroll
            for (int mb = 0; mb < 2; mb++)
                ldsm_x4(af[kt][mb],
                        sptr((const __half*)&alphas[w][16 * mb + lrow][0] + 16 * kt + lkoff));
        {
            unsigned d0, d1, d2, d3;
            ldsm_x4_trans(d0, d1, d2, d3, sptr(&hs[lane][cp]));
            unsigned bf0[2] = { d0, d1 };
            unsigned bf1[2] = { d2, d3 };
#pragma unroll
            for (int mb = 0; mb < 2; mb++) {
                mma_h(C[mb], af[0][mb], bf0);
                mma_h(C[mb], af[1][mb], bf1);
            }
        }

        float se = C[0][0] + C[0][2] + C[1][0] + C[1][2];
        float so = C[0][1] + C[0][3] + C[1][1] + C[1][3];
        u64 p = pack2(se, so);
        add2(p, shfl_xor_u64(p, 4));
        add2(p, shfl_xor_u64(p, 8));
        add2(p, shfl_xor_u64(p, 16));
        if (qr == 0 && qc < 3) {
            float2 pv = unpack2(p);
            cs[w * 6 + 2 * qc]     = pv.x * (1.f / 32.f) + b3[w * 6 + 2 * qc];
            cs[w * 6 + 2 * qc + 1] = pv.y * (1.f / 32.f) + b3[w * 6 + 2 * qc + 1];
        }
    }
    __syncthreads();

    // ---- final linear ----
    if (t < 64) {
        float acc = lb[t];
#pragma unroll
        for (int k = 0; k < F3; k++) acc = fmaf(cs[k], lw[k * 64 + t], acc);
        out[(size_t)g * 64 + t] = acc;
    }
}

extern "C" void kernel_launch(void* const* d_in, const int* in_sizes, int n_in,
                              void* d_out, int out_size)
{
    const float* xs  = (const float*)d_in[0];
    const float* pe  = (const float*)d_in[1];
    const float* W1  = (const float*)d_in[2];
    const float* as1 = (const float*)d_in[3];
    const float* ad1 = (const float*)d_in[4];
    const float* b1  = (const float*)d_in[5];
    const float* W2  = (const float*)d_in[6];
    const float* as2 = (const float*)d_in[7];
    const float* ad2 = (const float*)d_in[8];
    const float* b2  = (const float*)d_in[9];
    const float* W3  = (const float*)d_in[10];
    const float* as3 = (const float*)d_in[11];
    const float* ad3 = (const float*)d_in[12];
    const float* b3  = (const float*)d_in[13];
    const float* lw  = (const float*)d_in[14];
    const float* lb  = (const float*)d_in[15];
    float* out = (float*)d_out;

    int B = in_sizes[1] / (32 * 15);
    int R = in_sizes[0] / (B * 32);
    int G = B * R;

    prep_kernel<<<97, 128>>>(W1, W2, W3, as1, ad1, as2, ad2, as3, ad3);
    gat_fused_kernel<<<G, THREADS>>>(xs, pe, b1, b2, b3, lw, lb, out, R);
}

// round 16
// speedup vs baseline: 1.0747x; 1.0747x over previous
#include <cuda_runtime.h>
#include <cuda_fp16.h>

// GAT over 16384 independent 32-node cliques, fully fused: one CTA per graph.
// fp16 tensor cores; scores folded into GEMMs (pre-scaled by log2e); ldmatrix
// fragment loads; softmax runs in the exp2-fp16x2 domain (h2exp2, half MUFU).

#define NCOL 32
#define HEADS 4
#define FH 128
#define HSTR 136        // hs row stride in halfs
#define F3 24
#define XSTR 24
#define ASTRW 20        // alpha row stride in u32 words
#define THREADS 128
#define NEG_SLOPE 0.2f
#define LOG2E 1.4426950408889634f

typedef unsigned long long u64;

__device__ unsigned W2h_g[8192];   // fragment-ordered fp16x2 weights (uint4 units)
__device__ unsigned W1h_g[1024];
__device__ unsigned W3h_g[2048];
__device__ unsigned U1f_g[64];     // score vectors (W @ a) * log2e, fragment order
__device__ unsigned U2f_g[512];
__device__ unsigned U3f_g[512];

__device__ __forceinline__ float lrelu(float x) { return fmaxf(x, NEG_SLOPE * x); }

__device__ __forceinline__ u64 pack2(float a, float b) {
    u64 r; asm("mov.b64 %0,{%1,%2};" : "=l"(r) : "f"(a), "f"(b)); return r;
}
__device__ __forceinline__ float2 unpack2(u64 v) {
    float2 r; asm("mov.b64 {%0,%1},%2;" : "=f"(r.x), "=f"(r.y) : "l"(v)); return r;
}
__device__ __forceinline__ void add2(u64 &d, u64 a) {
    asm("add.rn.f32x2 %0,%0,%1;" : "+l"(d) : "l"(a));
}
__device__ __forceinline__ u64 shfl_xor_u64(u64 v, int m) {
    unsigned lo, hi;
    asm("mov.b64 {%0,%1},%2;" : "=r"(lo), "=r"(hi) : "l"(v));
    lo = __shfl_xor_sync(0xffffffffu, lo, m);
    hi = __shfl_xor_sync(0xffffffffu, hi, m);
    u64 r; asm("mov.b64 %0,{%1,%2};" : "=l"(r) : "r"(lo), "r"(hi));
    return r;
}
__device__ __forceinline__ unsigned packh2(float lo, float hi) {
    __half2 h = __floats2half2_rn(lo, hi);
    return *(unsigned*)&h;
}
__device__ __forceinline__ void mma_h(float c[4], const unsigned a[4], const unsigned b[2]) {
    asm("mma.sync.aligned.m16n8k16.row.col.f32.f16.f16.f32 "
        "{%0,%1,%2,%3}, {%4,%5,%6,%7}, {%8,%9}, {%0,%1,%2,%3};"
        : "+f"(c[0]), "+f"(c[1]), "+f"(c[2]), "+f"(c[3])
        : "r"(a[0]), "r"(a[1]), "r"(a[2]), "r"(a[3]), "r"(b[0]), "r"(b[1]));
}
__device__ __forceinline__ unsigned sptr(const void* p) {
    unsigned a;
    asm("{ .reg .u64 t; cvta.to.shared.u64 t, %1; cvt.u32.u64 %0, t; }" : "=r"(a) : "l"(p));
    return a;
}
__device__ __forceinline__ void ldsm_x4_trans(unsigned &d0, unsigned &d1,
                                              unsigned &d2, unsigned &d3, unsigned addr) {
    asm volatile("ldmatrix.sync.aligned.m8n8.x4.trans.shared.b16 {%0,%1,%2,%3}, [%4];"
                 : "=r"(d0), "=r"(d1), "=r"(d2), "=r"(d3) : "r"(addr));
}
__device__ __forceinline__ void ldsm_x4(unsigned a[4], unsigned addr) {
    asm volatile("ldmatrix.sync.aligned.m8n8.x4.shared.b16 {%0,%1,%2,%3}, [%4];"
                 : "=r"(a[0]), "=r"(a[1]), "=r"(a[2]), "=r"(a[3]) : "r"(addr));
}

__device__ __forceinline__ void store_scores(const float Cs[2][4],
                                             float* __restrict__ s_src,
                                             float* __restrict__ s_dst,
                                             int w, int qr, int qc)
{
    const int par = w & 1;
    if (qc == (w >> 1)) {
        s_src[32 * w + qr]      = par ? Cs[0][1] : Cs[0][0];
        s_src[32 * w + qr + 8]  = par ? Cs[0][3] : Cs[0][2];
        s_src[32 * w + qr + 16] = par ? Cs[1][1] : Cs[1][0];
        s_src[32 * w + qr + 24] = par ? Cs[1][3] : Cs[1][2];
    }
    if (qc == 2 + (w >> 1)) {
        s_dst[32 * w + qr]      = par ? Cs[0][1] : Cs[0][0];
        s_dst[32 * w + qr + 8]  = par ? Cs[0][3] : Cs[0][2];
        s_dst[32 * w + qr + 16] = par ? Cs[1][1] : Cs[1][0];
        s_dst[32 * w + qr + 24] = par ? Cs[1][3] : Cs[1][2];
    }
}

// Softmax in the exp2 domain (scores pre-scaled by log2e). Writes fp16 alpha.
__device__ __forceinline__ void softmax_exp2(
    const float* __restrict__ s_src, const float* __restrict__ s_dst,
    unsigned (*__restrict__ alpha)[ASTRW], int w, int lane)
{
    const float sdst = s_dst[w * NCOL + lane];
    unsigned ev[16];
    float sum = 0.f;
#pragma unroll
    for (int q = 0; q < 8; q++) {
        float4 sv = *(const float4*)&s_src[w * NCOL + 4 * q];
        __half2 p0 = __floats2half2_rn(lrelu(sdst + sv.x), lrelu(sdst + sv.y));
        __half2 p1 = __floats2half2_rn(lrelu(sdst + sv.z), lrelu(sdst + sv.w));
        __half2 e0 = h2exp2(p0);
        __half2 e1 = h2exp2(p1);
        ev[2 * q]     = *(unsigned*)&e0;
        ev[2 * q + 1] = *(unsigned*)&e1;
        float2 f0 = __half22float2(e0);
        float2 f1 = __half22float2(e1);
        sum += (f0.x + f0.y) + (f1.x + f1.y);
    }
    const __half2 rinv2 = __float2half2_rn(1.f / sum);
#pragma unroll
    for (int q = 0; q < 4; q++) {
        __half2 a0 = __hmul2(*(__half2*)&ev[4*q+0], rinv2);
        __half2 a1 = __hmul2(*(__half2*)&ev[4*q+1], rinv2);
        __half2 a2 = __hmul2(*(__half2*)&ev[4*q+2], rinv2);
        __half2 a3 = __hmul2(*(__half2*)&ev[4*q+3], rinv2);
        uint4 v;
        v.x = *(unsigned*)&a0; v.y = *(unsigned*)&a1;
        v.z = *(unsigned*)&a2; v.w = *(unsigned*)&a3;
        *(uint4*)&alpha[lane][4 * q] = v;
    }
}

__global__ void prep_kernel(const float* __restrict__ W1, const float* __restrict__ W2,
                            const float* __restrict__ W3,
                            const float* __restrict__ as1, const float* __restrict__ ad1,
                            const float* __restrict__ as2, const float* __restrict__ ad2,
                            const float* __restrict__ as3, const float* __restrict__ ad3)
{
    int idx = blockIdx.x * blockDim.x + threadIdx.x;
    if (idx < 8192) {            // W2h: (((w*4+nt)*4+m)*32+lane)*4+j  (uint4 units)
        int j = idx & 3, lane = (idx >> 2) & 31, m = (idx >> 7) & 3, unit = idx >> 9;
        int qr = lane >> 2, qc = lane & 3;
        int w = unit >> 2, nt = unit & 3;
        int kt = 2 * m + (j >> 1);
        int kp = 16 * kt + 2 * qc + ((j & 1) ? 8 : 0);
        int col = 32 * w + 8 * nt + qr;
        W2h_g[idx] = packh2(W2[kp * FH + col], W2[(kp + 1) * FH + col]);
    } else if (idx < 9216) {     // W1h
        int i = idx - 8192;
        int j = i & 1, lane = (i >> 1) & 31, unit = i >> 6;
        int qr = lane >> 2, qc = lane & 3;
        int w = unit >> 2, nt = unit & 3;
        int kp = 2 * qc + (j ? 8 : 0);
        int col = 32 * w + 8 * nt + qr;
        W1h_g[i] = packh2(W1[kp * FH + col], W1[(kp + 1) * FH + col]);
    } else if (idx < 11264) {    // W3h (padded n=qr, zero qr>=6)
        int i = idx - 9216;
        int j = i & 3, lane = (i >> 2) & 31, m = (i >> 7) & 3, w = i >> 9;
        int qr = lane >> 2, qc = lane & 3;
        int kt = 2 * m + (j >> 1);
        int kp = 16 * kt + 2 * qc + ((j & 1) ? 8 : 0);
        W3h_g[i] = (qr < 6) ? packh2(W3[kp * F3 + w * 6 + qr], W3[(kp + 1) * F3 + w * 6 + qr]) : 0u;
    } else if (idx < 11776) {    // U2f (x log2e)
        int i = idx - 11264;
        int jj = i & 3, lane = (i >> 2) & 31, m = i >> 7;
        int qr = lane >> 2, qc = lane & 3;
        int kt = 2 * m + (jj >> 1);
        int kp = 16 * kt + 2 * qc + ((jj & 1) ? 8 : 0);
        const float* av = (qr < 4) ? (as2 + 32 * qr) : (ad2 + 32 * (qr - 4));
        int h = qr & 3;
        float u0 = 0.f, u1 = 0.f;
        for (int d = 0; d < 32; d++) {
            u0 += W2[kp * FH + 32 * h + d] * av[d];
            u1 += W2[(kp + 1) * FH + 32 * h + d] * av[d];
        }
        U2f_g[i] = packh2(u0 * LOG2E, u1 * LOG2E);
    } else if (idx < 11840) {    // U1f (x log2e)
        int i = idx - 11776;
        int jj = i & 1, lane = i >> 1;
        int qr = lane >> 2, qc = lane & 3;
        int kp = 2 * qc + (jj ? 8 : 0);
        const float* av = (qr < 4) ? (as1 + 32 * qr) : (ad1 + 32 * (qr - 4));
        int h = qr & 3;
        float u0 = 0.f, u1 = 0.f;
        for (int d = 0; d < 32; d++) {
            u0 += W1[kp * FH + 32 * h + d] * av[d];
            u1 += W1[(kp + 1) * FH + 32 * h + d] * av[d];
        }
        U1f_g[i] = packh2(u0 * LOG2E, u1 * LOG2E);
    } else if (idx < 12352) {    // U3f (x log2e)
        int i = idx - 11840;
        int jj = i & 3, lane = (i >> 2) & 31, m = i >> 7;
        int qr = lane >> 2, qc = lane & 3;
        int kt = 2 * m + (jj >> 1);
        int kp = 16 * kt + 2 * qc + ((jj & 1) ? 8 : 0);
        const float* av = (qr < 4) ? (as3 + 6 * qr) : (ad3 + 6 * (qr - 4));
        int h = qr & 3;
        float u0 = 0.f, u1 = 0.f;
        for (int d = 0; d < 6; d++) {
            u0 += W3[kp * F3 + 6 * h + d] * av[d];
            u1 += W3[(kp + 1) * F3 + 6 * h + d] * av[d];
        }
        U3f_g[i] = packh2(u0 * LOG2E, u1 * LOG2E);
    }
}

__global__ void __launch_bounds__(THREADS, 6) gat_fused_kernel(
    const float* __restrict__ xs,
    const float* __restrict__ pe,
    const float* __restrict__ b1,
    const float* __restrict__ b2,
    const float* __restrict__ b3,
    const float* __restrict__ lw,
    const float* __restrict__ lb,
    float* __restrict__ out,
    int R)
{
    __shared__ __half hs[NCOL][HSTR];
    __shared__ unsigned alphas[HEADS][NCOL][ASTRW];
    __shared__ float s_src[HEADS * NCOL];
    __shared__ float s_dst[HEADS * NCOL];
    __shared__ float cs[F3];

    __half (*xin)[XSTR] = (__half(*)[XSTR]) & alphas[0][0][0];  // overlay

    const int g = blockIdx.x;
    const int b = g / R;
    const int r = g - b * R;
    const int t = threadIdx.x;
    const int lane = t & 31;
    const int w = t >> 5;
    const int qr = lane >> 2;
    const int qc = lane & 3;
    const int lrow = lane & 15;
    const int lkoff = (lane >> 4) << 3;

    // ---- build input features (fp16) ----
    for (int idx = t; idx < NCOL * 16; idx += THREADS) {
        int n = idx >> 4, f = idx & 15;
        float v;
        if (f == 0) v = xs[(size_t)(b * R + r) * NCOL + n];
        else        v = pe[(b * NCOL + n) * 15 + (f - 1)];
        xin[n][f] = __float2half_rn(v);
    }
    __syncthreads();

    // ================= layer 1 GEMM + scores =================
    {
        float C[2][4][4];
        float Cs[2][4];
#pragma unroll
        for (int mb = 0; mb < 2; mb++) {
#pragma unroll
            for (int nt = 0; nt < 4; nt++)
#pragma unroll
                for (int i = 0; i < 4; i++) C[mb][nt][i] = 0.f;
#pragma unroll
            for (int i = 0; i < 4; i++) Cs[mb][i] = 0.f;
        }

        unsigned a[2][4];
#pragma unroll
        for (int mb = 0; mb < 2; mb++)
            ldsm_x4(a[mb], sptr(&xin[16 * mb + lrow][lkoff]));

        const uint2* W1h2 = (const uint2*)W1h_g;
#pragma unroll
        for (int nt = 0; nt < 4; nt++) {
            uint2 bw = W1h2[(w * 4 + nt) * 32 + lane];
            unsigned bf[2] = { bw.x, bw.y };
#pragma unroll
            for (int mb = 0; mb < 2; mb++) mma_h(C[mb][nt], a[mb], bf);
        }
        {
            uint2 uw = ((const uint2*)U1f_g)[lane];
            unsigned bf[2] = { uw.x, uw.y };
#pragma unroll
            for (int mb = 0; mb < 2; mb++) mma_h(Cs[mb], a[mb], bf);
        }
#pragma unroll
        for (int mb = 0; mb < 2; mb++)
#pragma unroll
            for (int nt = 0; nt < 4; nt++) {
                const int c = 32 * w + 8 * nt + 2 * qc;
                *(unsigned*)&hs[16 * mb + qr][c]     = packh2(C[mb][nt][0], C[mb][nt][1]);
                *(unsigned*)&hs[16 * mb + qr + 8][c] = packh2(C[mb][nt][2], C[mb][nt][3]);
            }
        store_scores(Cs, s_src, s_dst, w, qr, qc);
    }
    __syncthreads();

    // ================= attention layers 1 & 2 + following GEMM =================
#pragma unroll
    for (int layer = 0; layer < 2; layer++) {
        const float* bias = layer ? b2 : b1;
        const int c0 = 32 * w;
        __syncwarp();

        softmax_exp2(s_src, s_dst, alphas[w], w, lane);
        __syncwarp();

        // aggregation MMA: out(32x32) = alpha @ h_head, in-place (warp-local cols)
        {
            float C[2][4][4];
#pragma unroll
            for (int mb = 0; mb < 2; mb++)
#pragma unroll
                for (int nt = 0; nt < 4; nt++)
#pragma unroll
                    for (int i = 0; i < 4; i++) C[mb][nt][i] = 0.f;

            unsigned af[2][2][4];
#pragma unroll
            for (int kt = 0; kt < 2; kt++)
#pragma unroll
                for (int mb = 0; mb < 2; mb++)
                    ldsm_x4(af[kt][mb],
                            sptr((const __half*)&alphas[w][16 * mb + lrow][0] + 16 * kt + lkoff));
#pragma unroll
            for (int nt = 0; nt < 4; nt++) {
                unsigned d0, d1, d2, d3;
                ldsm_x4_trans(d0, d1, d2, d3, sptr(&hs[lane][c0 + 8 * nt]));
                unsigned bf0[2] = { d0, d1 };
                unsigned bf1[2] = { d2, d3 };
#pragma unroll
                for (int mb = 0; mb < 2; mb++) {
                    mma_h(C[mb][nt], af[0][mb], bf0);
                    mma_h(C[mb][nt], af[1][mb], bf1);
                }
            }
            // epilogue: + bias, pack fp16, in-place store
#pragma unroll
            for (int nt = 0; nt < 4; nt++) {
                const int c = c0 + 8 * nt + 2 * qc;
                float bb0 = bias[c], bb1 = bias[c + 1];
#pragma unroll
                for (int mb = 0; mb < 2; mb++) {
                    *(unsigned*)&hs[16 * mb + qr][c] =
                        packh2(C[mb][nt][0] + bb0, C[mb][nt][1] + bb1);
                    *(unsigned*)&hs[16 * mb + qr + 8][c] =
                        packh2(C[mb][nt][2] + bb0, C[mb][nt][3] + bb1);
                }
            }
        }
        __syncthreads();

        if (layer == 0) {
            // ---- layer 2 GEMM + scores ----
            float C[2][4][4];
            float Cs[2][4];
#pragma unroll
            for (int mb = 0; mb < 2; mb++) {
#pragma unroll
                for (int nt = 0; nt < 4; nt++)
#pragma unroll
                    for (int i = 0; i < 4; i++) C[mb][nt][i] = 0.f;
#pragma unroll
                for (int i = 0; i < 4; i++) Cs[mb][i] = 0.f;
            }

            const uint4* W2h4 = (const uint4*)W2h_g;
            const uint4* U2f4 = (const uint4*)U2f_g;
#pragma unroll
            for (int m = 0; m < 4; m++) {
                uint4 wv[4];
#pragma unroll
                for (int nt = 0; nt < 4; nt++)
                    wv[nt] = W2h4[((w * 4 + nt) * 4 + m) * 32 + lane];
                uint4 uv = U2f4[m * 32 + lane];
#pragma unroll
                for (int hh = 0; hh < 2; hh++) {
                    const int kt = 2 * m + hh;
                    unsigned a[2][4];
#pragma unroll
                    for (int mb = 0; mb < 2; mb++)
                        ldsm_x4(a[mb], sptr(&hs[16 * mb + lrow][16 * kt + lkoff]));
#pragma unroll
                    for (int nt = 0; nt < 4; nt++) {
                        unsigned bf[2];
                        if (hh == 0) { bf[0] = wv[nt].x; bf[1] = wv[nt].y; }
                        else         { bf[0] = wv[nt].z; bf[1] = wv[nt].w; }
#pragma unroll
                        for (int mb = 0; mb < 2; mb++) mma_h(C[mb][nt], a[mb], bf);
                    }
                    {
                        unsigned bf[2];
                        if (hh == 0) { bf[0] = uv.x; bf[1] = uv.y; }
                        else         { bf[0] = uv.z; bf[1] = uv.w; }
#pragma unroll
                        for (int mb = 0; mb < 2; mb++) mma_h(Cs[mb], a[mb], bf);
                    }
                }
            }
            __syncthreads();
#pragma unroll
            for (int mb = 0; mb < 2; mb++)
#pragma unroll
                for (int nt = 0; nt < 4; nt++) {
                    const int c = 32 * w + 8 * nt + 2 * qc;
                    *(unsigned*)&hs[16 * mb + qr][c]     = packh2(C[mb][nt][0], C[mb][nt][1]);
                    *(unsigned*)&hs[16 * mb + qr + 8][c] = packh2(C[mb][nt][2], C[mb][nt][3]);
                }
            store_scores(Cs, s_src, s_dst, w, qr, qc);
        } else {
            // ---- layer 3 GEMM (padded cols 8w..8w+7) + scores ----
            float C[2][4];
            float Cs[2][4];
#pragma unroll
            for (int mb = 0; mb < 2; mb++)
#pragma unroll
                for (int i = 0; i < 4; i++) { C[mb][i] = 0.f; Cs[mb][i] = 0.f; }

            const uint4* W3h4 = (const uint4*)W3h_g;
            const uint4* U3f4 = (const uint4*)U3f_g;
#pragma unroll
            for (int m = 0; m < 4; m++) {
                uint4 wv = W3h4[(w * 4 + m) * 32 + lane];
                uint4 uv = U3f4[m * 32 + lane];
#pragma unroll
                for (int hh = 0; hh < 2; hh++) {
                    const int kt = 2 * m + hh;
                    unsigned a[2][4];
#pragma unroll
                    for (int mb = 0; mb < 2; mb++)
                        ldsm_x4(a[mb], sptr(&hs[16 * mb + lrow][16 * kt + lkoff]));
                    unsigned bf[2], bu[2];
                    if (hh == 0) { bf[0] = wv.x; bf[1] = wv.y; bu[0] = uv.x; bu[1] = uv.y; }
                    else         { bf[0] = wv.z; bf[1] = wv.w; bu[0] = uv.z; bu[1] = uv.w; }
#pragma unroll
                    for (int mb = 0; mb < 2; mb++) {
                        mma_h(C[mb], a[mb], bf);
                        mma_h(Cs[mb], a[mb], bu);
                    }
                }
            }
            __syncthreads();
#pragma unroll
            for (int mb = 0; mb < 2; mb++) {
                const int c = 8 * w + 2 * qc;
                *(unsigned*)&hs[16 * mb + qr][c]     = packh2(C[mb][0], C[mb][1]);
                *(unsigned*)&hs[16 * mb + qr + 8][c] = packh2(C[mb][2], C[mb][3]);
            }
            store_scores(Cs, s_src, s_dst, w, qr, qc);
        }
    }
    __syncwarp();

    // ================= layer-3 attention + register tail =================
    {
        const int cp = 8 * w;

        softmax_exp2(s_src, s_dst, alphas[w], w, lane);
        __syncwarp();

        // MMA: h3post = alpha @ h3 (N=8 padded); C stays in registers
        float C[2][4];
#pragma unroll
        for (int mb = 0; mb < 2; mb++)
#pragma unroll
            for (int i = 0; i < 4; i++) C[mb][i] = 0.f;

        unsigned af[2][2][4];
#pragma unroll
        for (int kt = 0; kt < 2; kt++)
#pragma unroll
            for (int mb = 0; mb < 2; mb++)
                ldsm_x4(af[kt][mb],
                        sptr((const __half*)&alphas[w][16 * mb + lrow][0] + 16 * kt + lkoff));
        {
            unsigned d0, d1, d2, d3;
            ldsm_x4_trans(d0, d1, d2, d3, sptr(&hs[lane][cp]));
            unsigned bf0[2] = { d0, d1 };
            unsigned bf1[2] = { d2, d3 };
#pragma unroll
            for (int mb = 0; mb < 2; mb++) {
                mma_h(C[mb], af[0][mb], bf0);
                mma_h(C[mb], af[1][mb], bf1);
            }
        }

        // tail: node-mean of h3post directly from C fragments
        float se = C[0][0] + C[0][2] + C[1][0] + C[1][2];
        float so = C[0][1] + C[0][3] + C[1][1] + C[1][3];
        u64 p = pack2(se, so);
        add2(p, shfl_xor_u64(p, 4));
        add2(p, shfl_xor_u64(p, 8));
        add2(p, shfl_xor_u64(p, 16));
        if (qr == 0 && qc < 3) {
            float2 pv = unpack2(p);
            cs[w * 6 + 2 * qc]     = pv.x * (1.f / 32.f) + b3[w * 6 + 2 * qc];
            cs[w * 6 + 2 * qc + 1] = pv.y * (1.f / 32.f) + b3[w * 6 + 2 * qc + 1];
        }
    }
    __syncthreads();

    // ---- final linear ----
    if (t < 64) {
        float acc = lb[t];
#pragma unroll
        for (int k = 0; k < F3; k++) acc = fmaf(cs[k], lw[k * 64 + t], acc);
        out[(size_t)g * 64 + t] = acc;
    }
}

extern "C" void kernel_launch(void* const* d_in, const int* in_sizes, int n_in,
                              void* d_out, int out_size)
{
    const float* xs  = (const float*)d_in[0];
    const float* pe  = (const float*)d_in[1];
    const float* W1  = (const float*)d_in[2];
    const float* as1 = (const float*)d_in[3];
    const float* ad1 = (const float*)d_in[4];
    const float* b1  = (const float*)d_in[5];
    const float* W2  = (const float*)d_in[6];
    const float* as2 = (const float*)d_in[7];
    const float* ad2 = (const float*)d_in[8];
    const float* b2  = (const float*)d_in[9];
    const float* W3  = (const float*)d_in[10];
    const float* as3 = (const float*)d_in[11];
    const float* ad3 = (const float*)d_in[12];
    const float* b3  = (const float*)d_in[13];
    const float* lw  = (const float*)d_in[14];
    const float* lb  = (const float*)d_in[15];
    float* out = (float*)d_out;

    int B = in_sizes[1] / (32 * 15);
    int R = in_sizes[0] / (B * 32);
    int G = B * R;

    prep_kernel<<<97, 128>>>(W1, W2, W3, as1, ad1, as2, ad2, as3, ad3);
    gat_fused_kernel<<<G, THREADS>>>(xs, pe, b1, b2, b3, lw, lb, out, R);
}

// round 17
// speedup vs baseline: 1.1246x; 1.0464x over previous
#include <cuda_runtime.h>
#include <cuda_fp16.h>

// GAT over 16384 independent 32-node cliques, fully fused: one CTA per graph.
// fp16 tensor cores; scores folded into GEMMs; exp2-domain softmax; ldmatrix
// fragment loads. This round: ping-pong hs buffers + separate xin cut the CTA
// barrier count 7 -> 4, and the attention aggregations accumulate in fp16
// (convex combination; D-frags store directly with packed-bias hadd2).

#define NCOL 32
#define HEADS 4
#define FH 128
#define HSTR 136        // hs row stride in halfs
#define F3 24
#define XSTR 24
#define ASTRW 20        // alpha row stride in u32 words
#define THREADS 128
#define NEG_SLOPE 0.2f
#define LOG2E 1.4426950408889634f

typedef unsigned long long u64;

__device__ unsigned W2h_g[8192];   // fragment-ordered fp16x2 weights (uint4 units)
__device__ unsigned W1h_g[1024];
__device__ unsigned W3h_g[2048];
__device__ unsigned U1f_g[64];     // score vectors (W @ a) * log2e, fragment order
__device__ unsigned U2f_g[512];
__device__ unsigned U3f_g[512];
__device__ unsigned B1h_g[64];     // biases packed half2
__device__ unsigned B2h_g[64];

__device__ __forceinline__ float lrelu(float x) { return fmaxf(x, NEG_SLOPE * x); }

__device__ __forceinline__ u64 pack2(float a, float b) {
    u64 r; asm("mov.b64 %0,{%1,%2};" : "=l"(r) : "f"(a), "f"(b)); return r;
}
__device__ __forceinline__ float2 unpack2(u64 v) {
    float2 r; asm("mov.b64 {%0,%1},%2;" : "=f"(r.x), "=f"(r.y) : "l"(v)); return r;
}
__device__ __forceinline__ void add2(u64 &d, u64 a) {
    asm("add.rn.f32x2 %0,%0,%1;" : "+l"(d) : "l"(a));
}
__device__ __forceinline__ u64 shfl_xor_u64(u64 v, int m) {
    unsigned lo, hi;
    asm("mov.b64 {%0,%1},%2;" : "=r"(lo), "=r"(hi) : "l"(v));
    lo = __shfl_xor_sync(0xffffffffu, lo, m);
    hi = __shfl_xor_sync(0xffffffffu, hi, m);
    u64 r; asm("mov.b64 %0,{%1,%2};" : "=l"(r) : "r"(lo), "r"(hi));
    return r;
}
__device__ __forceinline__ unsigned packh2(float lo, float hi) {
    __half2 h = __floats2half2_rn(lo, hi);
    return *(unsigned*)&h;
}
__device__ __forceinline__ unsigned hadd2u(unsigned a, unsigned b) {
    __half2 r = __hadd2(*(__half2*)&a, *(__half2*)&b);
    return *(unsigned*)&r;
}
__device__ __forceinline__ void mma_h(float c[4], const unsigned a[4], const unsigned b[2]) {
    asm("mma.sync.aligned.m16n8k16.row.col.f32.f16.f16.f32 "
        "{%0,%1,%2,%3}, {%4,%5,%6,%7}, {%8,%9}, {%0,%1,%2,%3};"
        : "+f"(c[0]), "+f"(c[1]), "+f"(c[2]), "+f"(c[3])
        : "r"(a[0]), "r"(a[1]), "r"(a[2]), "r"(a[3]), "r"(b[0]), "r"(b[1]));
}
__device__ __forceinline__ void mma_hh(unsigned c[2], const unsigned a[4], const unsigned b[2]) {
    asm("mma.sync.aligned.m16n8k16.row.col.f16.f16.f16.f16 "
        "{%0,%1}, {%2,%3,%4,%5}, {%6,%7}, {%0,%1};"
        : "+r"(c[0]), "+r"(c[1])
        : "r"(a[0]), "r"(a[1]), "r"(a[2]), "r"(a[3]), "r"(b[0]), "r"(b[1]));
}
__device__ __forceinline__ unsigned sptr(const void* p) {
    unsigned a;
    asm("{ .reg .u64 t; cvta.to.shared.u64 t, %1; cvt.u32.u64 %0, t; }" : "=r"(a) : "l"(p));
    return a;
}
__device__ __forceinline__ void ldsm_x4_trans(unsigned &d0, unsigned &d1,
                                              unsigned &d2, unsigned &d3, unsigned addr) {
    asm volatile("ldmatrix.sync.aligned.m8n8.x4.trans.shared.b16 {%0,%1,%2,%3}, [%4];"
                 : "=r"(d0), "=r"(d1), "=r"(d2), "=r"(d3) : "r"(addr));
}
__device__ __forceinline__ void ldsm_x4(unsigned a[4], unsigned addr) {
    asm volatile("ldmatrix.sync.aligned.m8n8.x4.shared.b16 {%0,%1,%2,%3}, [%4];"
                 : "=r"(a[0]), "=r"(a[1]), "=r"(a[2]), "=r"(a[3]) : "r"(addr));
}

__device__ __forceinline__ void store_scores(const float Cs[2][4],
                                             float* __restrict__ s_src,
                                             float* __restrict__ s_dst,
                                             int w, int qr, int qc)
{
    const int par = w & 1;
    if (qc == (w >> 1)) {
        s_src[32 * w + qr]      = par ? Cs[0][1] : Cs[0][0];
        s_src[32 * w + qr + 8]  = par ? Cs[0][3] : Cs[0][2];
        s_src[32 * w + qr + 16] = par ? Cs[1][1] : Cs[1][0];
        s_src[32 * w + qr + 24] = par ? Cs[1][3] : Cs[1][2];
    }
    if (qc == 2 + (w >> 1)) {
        s_dst[32 * w + qr]      = par ? Cs[0][1] : Cs[0][0];
        s_dst[32 * w + qr + 8]  = par ? Cs[0][3] : Cs[0][2];
        s_dst[32 * w + qr + 16] = par ? Cs[1][1] : Cs[1][0];
        s_dst[32 * w + qr + 24] = par ? Cs[1][3] : Cs[1][2];
    }
}

// Softmax in the exp2 domain (scores pre-scaled by log2e). Writes fp16 alpha.
__device__ __forceinline__ void softmax_exp2(
    const float* __restrict__ s_src, const float* __restrict__ s_dst,
    unsigned (*__restrict__ alpha)[ASTRW], int w, int lane)
{
    const float sdst = s_dst[w * NCOL + lane];
    unsigned ev[16];
    float sum = 0.f;
#pragma unroll
    for (int q = 0; q < 8; q++) {
        float4 sv = *(const float4*)&s_src[w * NCOL + 4 * q];
        __half2 p0 = __floats2half2_rn(lrelu(sdst + sv.x), lrelu(sdst + sv.y));
        __half2 p1 = __floats2half2_rn(lrelu(sdst + sv.z), lrelu(sdst + sv.w));
        __half2 e0 = h2exp2(p0);
        __half2 e1 = h2exp2(p1);
        ev[2 * q]     = *(unsigned*)&e0;
        ev[2 * q + 1] = *(unsigned*)&e1;
        float2 f0 = __half22float2(e0);
        float2 f1 = __half22float2(e1);
        sum += (f0.x + f0.y) + (f1.x + f1.y);
    }
    const __half2 rinv2 = __float2half2_rn(1.f / sum);
#pragma unroll
    for (int q = 0; q < 4; q++) {
        __half2 a0 = __hmul2(*(__half2*)&ev[4*q+0], rinv2);
        __half2 a1 = __hmul2(*(__half2*)&ev[4*q+1], rinv2);
        __half2 a2 = __hmul2(*(__half2*)&ev[4*q+2], rinv2);
        __half2 a3 = __hmul2(*(__half2*)&ev[4*q+3], rinv2);
        uint4 v;
        v.x = *(unsigned*)&a0; v.y = *(unsigned*)&a1;
        v.z = *(unsigned*)&a2; v.w = *(unsigned*)&a3;
        *(uint4*)&alpha[lane][4 * q] = v;
    }
}

// Attention aggregation, fp16 accumulation, in-place on hs cols 32w (warp-local).
__device__ __forceinline__ void attn_agg(
    __half (*__restrict__ hs)[HSTR], unsigned (*__restrict__ alpha)[ASTRW],
    const unsigned* __restrict__ biash,
    int w, int lane, int qr, int qc, int lrow, int lkoff)
{
    const int c0 = 32 * w;
    unsigned C[2][4][2];
#pragma unroll
    for (int mb = 0; mb < 2; mb++)
#pragma unroll
        for (int nt = 0; nt < 4; nt++) { C[mb][nt][0] = 0u; C[mb][nt][1] = 0u; }

    unsigned af[2][2][4];
#pragma unroll
    for (int kt = 0; kt < 2; kt++)
#pragma unroll
        for (int mb = 0; mb < 2; mb++)
            ldsm_x4(af[kt][mb],
                    sptr((const __half*)&alpha[16 * mb + lrow][0] + 16 * kt + lkoff));
#pragma unroll
    for (int nt = 0; nt < 4; nt++) {
        unsigned d0, d1, d2, d3;
        ldsm_x4_trans(d0, d1, d2, d3, sptr(&hs[lane][c0 + 8 * nt]));
        unsigned bf0[2] = { d0, d1 };
        unsigned bf1[2] = { d2, d3 };
#pragma unroll
        for (int mb = 0; mb < 2; mb++) {
            mma_hh(C[mb][nt], af[0][mb], bf0);
            mma_hh(C[mb][nt], af[1][mb], bf1);
        }
    }
    // epilogue: + packed fp16 bias, direct store (all reads precede writes)
#pragma unroll
    for (int nt = 0; nt < 4; nt++) {
        unsigned bw = biash[16 * w + 4 * nt + qc];
#pragma unroll
        for (int mb = 0; mb < 2; mb++) {
            *(unsigned*)&hs[16 * mb + qr][c0 + 8 * nt + 2 * qc]     = hadd2u(C[mb][nt][0], bw);
            *(unsigned*)&hs[16 * mb + qr + 8][c0 + 8 * nt + 2 * qc] = hadd2u(C[mb][nt][1], bw);
        }
    }
}

__global__ void prep_kernel(const float* __restrict__ W1, const float* __restrict__ W2,
                            const float* __restrict__ W3,
                            const float* __restrict__ as1, const float* __restrict__ ad1,
                            const float* __restrict__ as2, const float* __restrict__ ad2,
                            const float* __restrict__ as3, const float* __restrict__ ad3,
                            const float* __restrict__ b1, const float* __restrict__ b2)
{
    int idx = blockIdx.x * blockDim.x + threadIdx.x;
    if (idx < 8192) {            // W2h: (((w*4+nt)*4+m)*32+lane)*4+j  (uint4 units)
        int j = idx & 3, lane = (idx >> 2) & 31, m = (idx >> 7) & 3, unit = idx >> 9;
        int qr = lane >> 2, qc = lane & 3;
        int w = unit >> 2, nt = unit & 3;
        int kt = 2 * m + (j >> 1);
        int kp = 16 * kt + 2 * qc + ((j & 1) ? 8 : 0);
        int col = 32 * w + 8 * nt + qr;
        W2h_g[idx] = packh2(W2[kp * FH + col], W2[(kp + 1) * FH + col]);
    } else if (idx < 9216) {     // W1h
        int i = idx - 8192;
        int j = i & 1, lane = (i >> 1) & 31, unit = i >> 6;
        int qr = lane >> 2, qc = lane & 3;
        int w = unit >> 2, nt = unit & 3;
        int kp = 2 * qc + (j ? 8 : 0);
        int col = 32 * w + 8 * nt + qr;
        W1h_g[i] = packh2(W1[kp * FH + col], W1[(kp + 1) * FH + col]);
    } else if (idx < 11264) {    // W3h (padded n=qr, zero qr>=6)
        int i = idx - 9216;
        int j = i & 3, lane = (i >> 2) & 31, m = (i >> 7) & 3, w = i >> 9;
        int qr = lane >> 2, qc = lane & 3;
        int kt = 2 * m + (j >> 1);
        int kp = 16 * kt + 2 * qc + ((j & 1) ? 8 : 0);
        W3h_g[i] = (qr < 6) ? packh2(W3[kp * F3 + w * 6 + qr], W3[(kp + 1) * F3 + w * 6 + qr]) : 0u;
    } else if (idx < 11776) {    // U2f (x log2e)
        int i = idx - 11264;
        int jj = i & 3, lane = (i >> 2) & 31, m = i >> 7;
        int qr = lane >> 2, qc = lane & 3;
        int kt = 2 * m + (jj >> 1);
        int kp = 16 * kt + 2 * qc + ((jj & 1) ? 8 : 0);
        const float* av = (qr < 4) ? (as2 + 32 * qr) : (ad2 + 32 * (qr - 4));
        int h = qr & 3;
        float u0 = 0.f, u1 = 0.f;
        for (int d = 0; d < 32; d++) {
            u0 += W2[kp * FH + 32 * h + d] * av[d];
            u1 += W2[(kp + 1) * FH + 32 * h + d] * av[d];
        }
        U2f_g[i] = packh2(u0 * LOG2E, u1 * LOG2E);
    } else if (idx < 11840) {    // U1f (x log2e)
        int i = idx - 11776;
        int jj = i & 1, lane = i >> 1;
        int qr = lane >> 2, qc = lane & 3;
        int kp = 2 * qc + (jj ? 8 : 0);
        const float* av = (qr < 4) ? (as1 + 32 * qr) : (ad1 + 32 * (qr - 4));
        int h = qr & 3;
        float u0 = 0.f, u1 = 0.f;
        for (int d = 0; d < 32; d++) {
            u0 += W1[kp * FH + 32 * h + d] * av[d];
            u1 += W1[(kp + 1) * FH + 32 * h + d] * av[d];
        }
        U1f_g[i] = packh2(u0 * LOG2E, u1 * LOG2E);
    } else if (idx < 12352) {    // U3f (x log2e)
        int i = idx - 11840;
        int jj = i & 3, lane = (i >> 2) & 31, m = i >> 7;
        int qr = lane >> 2, qc = lane & 3;
        int kt = 2 * m + (jj >> 1);
        int kp = 16 * kt + 2 * qc + ((jj & 1) ? 8 : 0);
        const float* av = (qr < 4) ? (as3 + 6 * qr) : (ad3 + 6 * (qr - 4));
        int h = qr & 3;
        float u0 = 0.f, u1 = 0.f;
        for (int d = 0; d < 6; d++) {
            u0 += W3[kp * F3 + 6 * h + d] * av[d];
            u1 += W3[(kp + 1) * F3 + 6 * h + d] * av[d];
        }
        U3f_g[i] = packh2(u0 * LOG2E, u1 * LOG2E);
    } else if (idx < 12416) {    // B1h
        int i = idx - 12352;
        B1h_g[i] = packh2(b1[2 * i], b1[2 * i + 1]);
    } else if (idx < 12480) {    // B2h
        int i = idx - 12416;
        B2h_g[i] = packh2(b2[2 * i], b2[2 * i + 1]);
    }
}

__global__ void __launch_bounds__(THREADS, 6) gat_fused_kernel(
    const float* __restrict__ xs,
    const float* __restrict__ pe,
    const float* __restrict__ b3,
    const float* __restrict__ lw,
    const float* __restrict__ lb,
    float* __restrict__ out,
    int R)
{
    __shared__ __half hsA[NCOL][HSTR];
    __shared__ __half hsB[NCOL][HSTR];
    __shared__ unsigned alphas[HEADS][NCOL][ASTRW];
    __shared__ __half xin[NCOL][XSTR];
    __shared__ float s_src[HEADS * NCOL];
    __shared__ float s_dst[HEADS * NCOL];
    __shared__ float cs[F3];

    const int g = blockIdx.x;
    const int b = g / R;
    const int r = g - b * R;
    const int t = threadIdx.x;
    const int lane = t & 31;
    const int w = t >> 5;
    const int qr = lane >> 2;
    const int qc = lane & 3;
    const int lrow = lane & 15;
    const int lkoff = (lane >> 4) << 3;

    // ---- build input features (fp16) ----
    for (int idx = t; idx < NCOL * 16; idx += THREADS) {
        int n = idx >> 4, f = idx & 15;
        float v;
        if (f == 0) v = xs[(size_t)(b * R + r) * NCOL + n];
        else        v = pe[(b * NCOL + n) * 15 + (f - 1)];
        xin[n][f] = __float2half_rn(v);
    }
    __syncthreads();   // B1: xin visible to all warps

    // ================= layer 1 GEMM + scores (xin -> hsA cols 32w) =================
    {
        float C[2][4][4];
        float Cs[2][4];
#pragma unroll
        for (int mb = 0; mb < 2; mb++) {
#pragma unroll
            for (int nt = 0; nt < 4; nt++)
#pragma unroll
                for (int i = 0; i < 4; i++) C[mb][nt][i] = 0.f;
#pragma unroll
            for (int i = 0; i < 4; i++) Cs[mb][i] = 0.f;
        }

        unsigned a[2][4];
#pragma unroll
        for (int mb = 0; mb < 2; mb++)
            ldsm_x4(a[mb], sptr(&xin[16 * mb + lrow][lkoff]));

        const uint2* W1h2 = (const uint2*)W1h_g;
#pragma unroll
        for (int nt = 0; nt < 4; nt++) {
            uint2 bw = W1h2[(w * 4 + nt) * 32 + lane];
            unsigned bf[2] = { bw.x, bw.y };
#pragma unroll
            for (int mb = 0; mb < 2; mb++) mma_h(C[mb][nt], a[mb], bf);
        }
        {
            uint2 uw = ((const uint2*)U1f_g)[lane];
            unsigned bf[2] = { uw.x, uw.y };
#pragma unroll
            for (int mb = 0; mb < 2; mb++) mma_h(Cs[mb], a[mb], bf);
        }
#pragma unroll
        for (int mb = 0; mb < 2; mb++)
#pragma unroll
            for (int nt = 0; nt < 4; nt++) {
                const int c = 32 * w + 8 * nt + 2 * qc;
                *(unsigned*)&hsA[16 * mb + qr][c]     = packh2(C[mb][nt][0], C[mb][nt][1]);
                *(unsigned*)&hsA[16 * mb + qr + 8][c] = packh2(C[mb][nt][2], C[mb][nt][3]);
            }
        store_scores(Cs, s_src, s_dst, w, qr, qc);
    }
    __syncwarp();

    // ---- attn1 on hsA (warp-local, fp16 accumulation) ----
    softmax_exp2(s_src, s_dst, alphas[w], w, lane);
    __syncwarp();
    attn_agg(hsA, alphas[w], B1h_g, w, lane, qr, qc, lrow, lkoff);
    __syncthreads();   // B2: hsA visible for GEMM2 A-fragments

    // ================= layer 2 GEMM + scores (hsA -> hsB cols 32w) =================
    {
        float C[2][4][4];
        float Cs[2][4];
#pragma unroll
        for (int mb = 0; mb < 2; mb++) {
#pragma unroll
            for (int nt = 0; nt < 4; nt++)
#pragma unroll
                for (int i = 0; i < 4; i++) C[mb][nt][i] = 0.f;
#pragma unroll
            for (int i = 0; i < 4; i++) Cs[mb][i] = 0.f;
        }

        const uint4* W2h4 = (const uint4*)W2h_g;
        const uint4* U2f4 = (const uint4*)U2f_g;
#pragma unroll
        for (int m = 0; m < 4; m++) {
            uint4 wv[4];
#pragma unroll
            for (int nt = 0; nt < 4; nt++)
                wv[nt] = W2h4[((w * 4 + nt) * 4 + m) * 32 + lane];
            uint4 uv = U2f4[m * 32 + lane];
#pragma unroll
            for (int hh = 0; hh < 2; hh++) {
                const int kt = 2 * m + hh;
                unsigned a[2][4];
#pragma unroll
                for (int mb = 0; mb < 2; mb++)
                    ldsm_x4(a[mb], sptr(&hsA[16 * mb + lrow][16 * kt + lkoff]));
#pragma unroll
                for (int nt = 0; nt < 4; nt++) {
                    unsigned bf[2];
                    if (hh == 0) { bf[0] = wv[nt].x; bf[1] = wv[nt].y; }
                    else         { bf[0] = wv[nt].z; bf[1] = wv[nt].w; }
#pragma unroll
                    for (int mb = 0; mb < 2; mb++) mma_h(C[mb][nt], a[mb], bf);
                }
                {
                    unsigned bf[2];
                    if (hh == 0) { bf[0] = uv.x; bf[1] = uv.y; }
                    else         { bf[0] = uv.z; bf[1] = uv.w; }
#pragma unroll
                    for (int mb = 0; mb < 2; mb++) mma_h(Cs[mb], a[mb], bf);
                }
            }
        }
        // write to hsB: no pre-store barrier needed (different buffer)
#pragma unroll
        for (int mb = 0; mb < 2; mb++)
#pragma unroll
            for (int nt = 0; nt < 4; nt++) {
                const int c = 32 * w + 8 * nt + 2 * qc;
                *(unsigned*)&hsB[16 * mb + qr][c]     = packh2(C[mb][nt][0], C[mb][nt][1]);
                *(unsigned*)&hsB[16 * mb + qr + 8][c] = packh2(C[mb][nt][2], C[mb][nt][3]);
            }
        store_scores(Cs, s_src, s_dst, w, qr, qc);
    }
    __syncwarp();

    // ---- attn2 on hsB (warp-local, fp16 accumulation) ----
    softmax_exp2(s_src, s_dst, alphas[w], w, lane);
    __syncwarp();
    attn_agg(hsB, alphas[w], B2h_g, w, lane, qr, qc, lrow, lkoff);
    __syncthreads();   // B3: hsB visible for GEMM3 A-fragments

    // ================= layer 3 GEMM + scores (hsB -> hsA padded cols 8w) ============
    {
        float C[2][4];
        float Cs[2][4];
#pragma unroll
        for (int mb = 0; mb < 2; mb++)
#pragma unroll
            for (int i = 0; i < 4; i++) { C[mb][i] = 0.f; Cs[mb][i] = 0.f; }

        const uint4* W3h4 = (const uint4*)W3h_g;
        const uint4* U3f4 = (const uint4*)U3f_g;
#pragma unroll
        for (int m = 0; m < 4; m++) {
            uint4 wv = W3h4[(w * 4 + m) * 32 + lane];
            uint4 uv = U3f4[m * 32 + lane];
#pragma unroll
            for (int hh = 0; hh < 2; hh++) {
                const int kt = 2 * m + hh;
                unsigned a[2][4];
#pragma unroll
                for (int mb = 0; mb < 2; mb++)
                    ldsm_x4(a[mb], sptr(&hsB[16 * mb + lrow][16 * kt + lkoff]));
                unsigned bf[2], bu[2];
                if (hh == 0) { bf[0] = wv.x; bf[1] = wv.y; bu[0] = uv.x; bu[1] = uv.y; }
                else         { bf[0] = wv.z; bf[1] = wv.w; bu[0] = uv.z; bu[1] = uv.w; }
#pragma unroll
                for (int mb = 0; mb < 2; mb++) {
                    mma_h(C[mb], a[mb], bf);
                    mma_h(Cs[mb], a[mb], bu);
                }
            }
        }
        // write to hsA cols 8w: safe, all hsA readers finished at B3
#pragma unroll
        for (int mb = 0; mb < 2; mb++) {
            const int c = 8 * w + 2 * qc;
            *(unsigned*)&hsA[16 * mb + qr][c]     = packh2(C[mb][0], C[mb][1]);
            *(unsigned*)&hsA[16 * mb + qr + 8][c] = packh2(C[mb][2], C[mb][3]);
        }
        store_scores(Cs, s_src, s_dst, w, qr, qc);
    }
    __syncwarp();

    // ================= layer-3 attention + register tail (on hsA) ===================
    {
        const int cp = 8 * w;

        softmax_exp2(s_src, s_dst, alphas[w], w, lane);
        __syncwarp();

        float C[2][4];
#pragma unroll
        for (int mb = 0; mb < 2; mb++)
#pragma unroll
            for (int i = 0; i < 4; i++) C[mb][i] = 0.f;

        unsigned af[2][2][4];
#pragma unroll
        for (int kt = 0; kt < 2; kt++)
#pragma unroll
            for (int mb = 0; mb < 2; mb++)
                ldsm_x4(af[kt][mb],
                        sptr((const __half*)&alphas[w][16 * mb + lrow][0] + 16 * kt + lkoff));
        {
            unsigned d0, d1, d2, d3;
            ldsm_x4_trans(d0, d1, d2, d3, sptr(&hsA[lane][cp]));
            unsigned bf0[2] = { d0, d1 };
            unsigned bf1[2] = { d2, d3 };
#pragma unroll
            for (int mb = 0; mb < 2; mb++) {
                mma_h(C[mb], af[0][mb], bf0);
                mma_h(C[mb], af[1][mb], bf1);
            }
        }

        float se = C[0][0] + C[0][2] + C[1][0] + C[1][2];
        float so = C[0][1] + C[0][3] + C[1][1] + C[1][3];
        u64 p = pack2(se, so);
        add2(p, shfl_xor_u64(p, 4));
        add2(p, shfl_xor_u64(p, 8));
        add2(p, shfl_xor_u64(p, 16));
        if (qr == 0 && qc < 3) {
            float2 pv = unpack2(p);
            cs[w * 6 + 2 * qc]     = pv.x * (1.f / 32.f) + b3[w * 6 + 2 * qc];
            cs[w * 6 + 2 * qc + 1] = pv.y * (1.f / 32.f) + b3[w * 6 + 2 * qc + 1];
        }
    }
    __syncthreads();   // B4: cs visible

    // ---- final linear ----
    if (t < 64) {
        float acc = lb[t];
#pragma unroll
        for (int k = 0; k < F3; k++) acc = fmaf(cs[k], lw[k * 64 + t], acc);
        out[(size_t)g * 64 + t] = acc;
    }
}

extern "C" void kernel_launch(void* const* d_in, const int* in_sizes, int n_in,
                              void* d_out, int out_size)
{
    const float* xs  = (const float*)d_in[0];
    const float* pe  = (const float*)d_in[1];
    const float* W1  = (const float*)d_in[2];
    const float* as1 = (const float*)d_in[3];
    const float* ad1 = (const float*)d_in[4];
    const float* b1  = (const float*)d_in[5];
    const float* W2  = (const float*)d_in[6];
    const float* as2 = (const float*)d_in[7];
    const float* ad2 = (const float*)d_in[8];
    const float* b2  = (const float*)d_in[9];
    const float* W3  = (const float*)d_in[10];
    const float* as3 = (const float*)d_in[11];
    const float* ad3 = (const float*)d_in[12];
    const float* b3  = (const float*)d_in[13];
    const float* lw  = (const float*)d_in[14];
    const float* lb  = (const float*)d_in[15];
    float* out = (float*)d_out;

    int B = in_sizes[1] / (32 * 15);
    int R = in_sizes[0] / (B * 32);
    int G = B * R;

    prep_kernel<<<98, 128>>>(W1, W2, W3, as1, ad1, as2, ad2, as3, ad3, b1, b2);
    gat_fused_kernel<<<G, THREADS>>>(xs, pe, b3, lw, lb, out, R);
}